// round 4
// baseline (speedup 1.0000x reference)
#include <cuda_runtime.h>
#include <cuda_fp16.h>
#include <math.h>

#define BB 8
#define CC 16
#define HH 240
#define WW 320
#define NN (HH*WW)
#define BCN (BB*CC*NN)
#define ITER_BLOCKS (NN/2/256*BB)   // 150*8 = 1200

// ---------------- device-global state (no allocations allowed) ----------------
__device__ float g_R[BB][9];
__device__ float g_t[BB][3];
__device__ float g_acc[BB][27];            // 21 upper-tri JtWJ + 6 Rhs
__device__ unsigned int g_count;           // last-block counter (zero-init, reset each use)
// channel-innermost packed layouts (pixel-major blocks):
//   g_cen : per pixel 16 x uint2 {half2(a,g), half2(x0, sigma0^2)} = 128B
//   g_gath: per pixel 16 x half2 {x1, sigma1}                      = 64B
__device__ uint2   g_cen[BCN];
__device__ __half2 g_gath[BCN];

__device__ __forceinline__ unsigned pack_h2(float a, float b) {
    __half2 h = __floats2half2_rn(a, b);
    return *(unsigned*)&h;
}
__device__ __forceinline__ __half2 as_h2(unsigned u) { return *(__half2*)&u; }

__device__ __forceinline__ void rodrigues(float wx, float wy, float wz, float* R) {
    float th = sqrtf(wx*wx + wy*wy + wz*wz) + 1e-12f;
    float inv = 1.0f / th;
    float ax = wx*inv, ay = wy*inv, az = wz*inv;
    float s = sinf(th), c = cosf(th), mc = 1.0f - c;
    R[0] = c + mc*ax*ax;     R[1] = mc*ax*ay - s*az;  R[2] = mc*ax*az + s*ay;
    R[3] = mc*ax*ay + s*az;  R[4] = c + mc*ay*ay;     R[5] = mc*ay*az - s*ax;
    R[6] = mc*ax*az - s*ay;  R[7] = mc*ay*az + s*ax;  R[8] = c + mc*az*az;
}

// ---------------- pack: sobel + fp16 pack to channel-innermost; init fused ----------------
__global__ __launch_bounds__(256)
void packKernel(const float* __restrict__ twist0, const float* __restrict__ x0,
                const float* __restrict__ sigma0, const float* __restrict__ x1,
                const float* __restrict__ sigma1) {
    int t = blockIdx.x * 256 + threadIdx.x;         // one thread = 2 horizontal pixels, all channels
    if (blockIdx.x == 0 && threadIdx.x < BB) {      // fused init
        int b = threadIdx.x;
        rodrigues(twist0[b*6+0], twist0[b*6+1], twist0[b*6+2], g_R[b]);
        g_t[b][0] = twist0[b*6+3];
        g_t[b][1] = twist0[b*6+4];
        g_t[b][2] = twist0[b*6+5];
#pragma unroll
        for (int k = 0; k < 27; k++) g_acc[b][k] = 0.0f;
    }

    int plin = t * 2;                                // global pixel index over B*N
    int b = plin / NN;
    int p = plin - b*NN;
    int v  = p / WW;
    int u0 = p - v*WW;                               // even, pair stays in row

    int vm = max(v-1, 0)*WW, v0r = v*WW, vp = min(v+1, HH-1)*WW;
    int ul = max(u0-1, 0), ur = min(u0+2, WW-1);

    size_t pix0 = (size_t)b*NN + p;                  // pixel-major block index
    uint4* cenOut  = (uint4*)g_cen  + pix0*8;        // 8 uint4 per pixel
    uint4* gathOut = (uint4*)g_gath + pix0*4;        // 4 uint4 per pixel

#pragma unroll
    for (int cb = 0; cb < 4; cb++) {
        uint4 cA0, cB0, cA1, cB1, gq0, gq1;
        unsigned* cen0 = (unsigned*)&cA0;            // [4] = two channels' {ag, xs}
        unsigned* cen0b = (unsigned*)&cB0;
        unsigned* cen1 = (unsigned*)&cA1;
        unsigned* cen1b = (unsigned*)&cB1;
        unsigned* gg0 = (unsigned*)&gq0;
        unsigned* gg1 = (unsigned*)&gq1;
#pragma unroll
        for (int j = 0; j < 4; j++) {
            int c = cb*4 + j;
            const float* img = x0 + (size_t)(b*CC + c)*NN;
            float  ta = img[vm + ul];
            float2 tm = *(const float2*)(img + vm + u0);
            float  tr = img[vm + ur];
            float  ma = img[v0r + ul];
            float2 mm = *(const float2*)(img + v0r + u0);
            float  mr = img[v0r + ur];
            float  ba = img[vp + ul];
            float2 bm = *(const float2*)(img + vp + u0);
            float  br = img[vp + ur];

            // pixel 0: cols (ul, u0, u0+1)
            float dx0 = tm.y - ta + 2.0f*(mm.y - ma) + (bm.y - ba);
            float dy0 = ba - ta + 2.0f*(bm.x - tm.x) + (bm.y - tm.y);
            float r0 = rsqrtf(dx0*dx0 + dy0*dy0 + 1e-8f);
            // pixel 1: cols (u0, u0+1, ur)
            float dx1 = tr - tm.x + 2.0f*(mr - mm.x) + (br - bm.x);
            float dy1 = bm.x - tm.x + 2.0f*(bm.y - tm.y) + (br - tr);
            float r1 = rsqrtf(dx1*dx1 + dy1*dy1 + 1e-8f);

            size_t off = (size_t)(b*CC + c)*NN + p;
            float2 s0 = *(const float2*)(sigma0 + off);
            float2 xv = *(const float2*)(x1 + off);
            float2 sv = *(const float2*)(sigma1 + off);

            unsigned ag0 = pack_h2(dx0*r0, dy0*r0);
            unsigned xs0 = pack_h2(mm.x, s0.x*s0.x);
            unsigned ag1 = pack_h2(dx1*r1, dy1*r1);
            unsigned xs1 = pack_h2(mm.y, s0.y*s0.y);
            if (j < 2) { cen0[j*2] = ag0; cen0[j*2+1] = xs0; cen1[j*2] = ag1; cen1[j*2+1] = xs1; }
            else       { cen0b[(j-2)*2] = ag0; cen0b[(j-2)*2+1] = xs0; cen1b[(j-2)*2] = ag1; cen1b[(j-2)*2+1] = xs1; }
            gg0[j] = pack_h2(xv.x, sv.x);
            gg1[j] = pack_h2(xv.y, sv.y);
        }
        cenOut[cb*2]   = cA0;  cenOut[cb*2+1]   = cB0;
        cenOut[8 + cb*2] = cA1; cenOut[8 + cb*2+1] = cB1;  // pixel 1 block follows pixel 0
        gathOut[cb]      = gq0;
        gathOut[4 + cb]  = gq1;
    }
}

// ---------------- fused per-iteration accumulation + last-block solve ----------------
__global__ __launch_bounds__(256)
void iterKernel(const float* __restrict__ invD0, const float* __restrict__ invD1,
                const float* __restrict__ Kmat, float* __restrict__ out, int last)
{
    const int b  = blockIdx.y;
    const int p2 = (blockIdx.x * 256 + threadIdx.x) * 2;

    float acc[27];
#pragma unroll
    for (int k = 0; k < 27; k++) acc[k] = 0.0f;

    {
        const float fx = Kmat[b*4+0], fy = Kmat[b*4+1];
        const float cx = Kmat[b*4+2], cy = Kmat[b*4+3];
        const float ifx = 1.0f/fx, ify = 1.0f/fy;
        const float* Rb = g_R[b];
        const float* tb = g_t[b];

        int vpix = p2 / WW;
        int u0   = p2 - vpix*WW;
        float y  = ((float)vpix - cy) * ify;
        float2 d2 = *(const float2*)(invD0 + (size_t)b*NN + p2);
        float dd[2] = {d2.x, d2.y};

        float xs_[2], valid[2];
        __half2 w00h[2], w01h[2], w10h[2], w11h[2];
        int o00[2], o01[2], o10[2], o11[2];
        const float* D1 = invD1 + (size_t)b*NN;

#pragma unroll
        for (int i = 0; i < 2; i++) {
            float x = ((float)(u0 + i) - cx) * ifx;
            xs_[i] = x;
            float d = dd[i];
            float X = Rb[0]*x + Rb[1]*y + Rb[2] + tb[0]*d;
            float Y = Rb[3]*x + Rb[4]*y + Rb[5] + tb[1]*d;
            float S = Rb[6]*x + Rb[7]*y + Rb[8] + tb[2]*d;
            float invS = __fdividef(1.0f, S);
            float u = X * invS * fx + cx;
            float v = Y * invS * fy + cy;
            float invz = d * invS;

            float uc = fminf(fmaxf(u, 0.0f), (float)(WW-1));
            float vc = fminf(fmaxf(v, 0.0f), (float)(HH-1));
            float x0f = floorf(uc), y0f = floorf(vc);
            float wx = uc - x0f, wy = vc - y0f;
            int xi0 = (int)x0f, yi0 = (int)y0f;
            int xi1 = min(xi0 + 1, WW-1), yi1 = min(yi0 + 1, HH-1);
            float w00 = (1.0f-wx)*(1.0f-wy), w01 = wx*(1.0f-wy);
            float w10 = (1.0f-wx)*wy,        w11 = wx*wy;
            o00[i] = yi0*WW + xi0; o01[i] = yi0*WW + xi1;
            o10[i] = yi1*WW + xi0; o11[i] = yi1*WW + xi1;
            w00h[i] = __float2half2_rn(w00); w01h[i] = __float2half2_rn(w01);
            w10h[i] = __float2half2_rn(w10); w11h[i] = __float2half2_rn(w11);

            float dz = D1[o00[i]]*w00 + D1[o01[i]]*w01 + D1[o10[i]]*w10 + D1[o11[i]]*w11;
            bool inlier = invz > dz - 0.1f;
            bool inview = (u > 0.0f) && (u < (float)WW) && (v > 0.0f) && (v < (float)HH);
            valid[i] = (inlier && inview) ? 1.0f : 0.0f;
        }

        float Saa[2] = {0,0}, Sab[2] = {0,0}, Sbb[2] = {0,0};
        float Sar[2] = {0,0}, Sbr[2] = {0,0};
#pragma unroll
        for (int i = 0; i < 2; i++) {
            const uint4* cenP = (const uint4*)g_cen + ((size_t)b*NN + p2 + i)*8;
            const uint4* G00 = (const uint4*)g_gath + ((size_t)b*NN + o00[i])*4;
            const uint4* G01 = (const uint4*)g_gath + ((size_t)b*NN + o01[i])*4;
            const uint4* G10 = (const uint4*)g_gath + ((size_t)b*NN + o10[i])*4;
            const uint4* G11 = (const uint4*)g_gath + ((size_t)b*NN + o11[i])*4;
            __half2 W00 = w00h[i], W01 = w01h[i], W10 = w10h[i], W11 = w11h[i];
#pragma unroll
            for (int cb = 0; cb < 4; cb++) {
                uint4 q00 = __ldg(G00 + cb);
                uint4 q01 = __ldg(G01 + cb);
                uint4 q10 = __ldg(G10 + cb);
                uint4 q11 = __ldg(G11 + cb);
                uint4 cA  = __ldg(cenP + cb*2);
                uint4 cB  = __ldg(cenP + cb*2 + 1);
                const unsigned* u00 = (const unsigned*)&q00;
                const unsigned* u01 = (const unsigned*)&q01;
                const unsigned* u10 = (const unsigned*)&q10;
                const unsigned* u11 = (const unsigned*)&q11;
                const unsigned* cen = (const unsigned*)&cA;   // cA.x..w, cB.x..w contiguous? keep split
                const unsigned* cen2 = (const unsigned*)&cB;
#pragma unroll
                for (int j = 0; j < 4; j++) {
                    __half2 fs = __hmul2(as_h2(u00[j]), W00);
                    fs = __hfma2(as_h2(u01[j]), W01, fs);
                    fs = __hfma2(as_h2(u10[j]), W10, fs);
                    fs = __hfma2(as_h2(u11[j]), W11, fs);
                    float2 frsr = __half22float2(fs);
                    unsigned agu = (j < 2) ? cen[j*2]   : cen2[(j-2)*2];
                    unsigned xsu = (j < 2) ? cen[j*2+1] : cen2[(j-2)*2+1];
                    float2 ag  = __half22float2(as_h2(agu));
                    float2 xss = __half22float2(as_h2(xsu));
                    float s2  = frsr.y*frsr.y + xss.y;
                    float wgt = __fdividef(1.0f, s2);
                    float res = frsr.x - xss.x;
                    float aw = ag.x*wgt, gw = ag.y*wgt;
                    Saa[i] += aw*ag.x;
                    Sab[i] += aw*ag.y;
                    Sbb[i] += gw*ag.y;
                    Sar[i] += aw*res;
                    Sbr[i] += gw*res;
                }
            }
        }

        // expand each pixel's S into 27 accumulators
#pragma unroll
        for (int i = 0; i < 2; i++) {
            float vmask = valid[i];
            float saa = Saa[i]*vmask, sab = Sab[i]*vmask, sbb = Sbb[i]*vmask;
            float sar = Sar[i]*vmask, sbr = Sbr[i]*vmask;
            float x = xs_[i], d = dd[i];
            float xy = x*y;
            float Jx[6], Jy[6];
            Jx[0] = -xy*fx;          Jx[1] = (1.0f + x*x)*fx; Jx[2] = -y*fx;
            Jx[3] = d*fx;            Jx[4] = 0.0f;            Jx[5] = -d*x*fx;
            Jy[0] = -(1.0f+y*y)*fy;  Jy[1] = xy*fy;           Jy[2] = x*fy;
            Jy[3] = 0.0f;            Jy[4] = d*fy;            Jy[5] = -d*y*fy;
            int idx = 0;
#pragma unroll
            for (int k = 0; k < 6; k++) {
#pragma unroll
                for (int l = k; l < 6; l++) {
                    acc[idx++] += saa*Jx[k]*Jx[l] + sab*(Jx[k]*Jy[l] + Jy[k]*Jx[l]) + sbb*Jy[k]*Jy[l];
                }
            }
#pragma unroll
            for (int k = 0; k < 6; k++) acc[21+k] += sar*Jx[k] + sbr*Jy[k];
        }
    }

    // ---- block reduction of 27 values, then per-block atomicAdd ----
#pragma unroll
    for (int k = 0; k < 27; k++) {
#pragma unroll
        for (int off = 16; off > 0; off >>= 1)
            acc[k] += __shfl_down_sync(0xFFFFFFFFu, acc[k], off);
    }
    __shared__ float sm[27][8];
    int lane = threadIdx.x & 31;
    int warp = threadIdx.x >> 5;
    if (lane == 0) {
#pragma unroll
        for (int k = 0; k < 27; k++) sm[k][warp] = acc[k];
    }
    __syncthreads();
    if (threadIdx.x < 27) {
        float s = 0.0f;
#pragma unroll
        for (int w = 0; w < 8; w++) s += sm[threadIdx.x][w];
        atomicAdd(&g_acc[blockIdx.y][threadIdx.x], s);
        __threadfence();
    }
    __syncthreads();

    // ---- last-block-does-solve (threadFenceReduction pattern) ----
    __shared__ bool sLast;
    if (threadIdx.x == 0) {
        unsigned int done = atomicAdd(&g_count, 1u);
        sLast = (done == ITER_BLOCKS - 1);
    }
    __syncthreads();
    if (!sLast) return;
    if (threadIdx.x == 0) g_count = 0;
    __threadfence();

    if (threadIdx.x < BB) {
        int bb = threadIdx.x;
        float M[6][7];
        {
            float Jt[6][6];
            int idx = 0;
#pragma unroll
            for (int k = 0; k < 6; k++)
#pragma unroll
                for (int l = k; l < 6; l++) {
                    float vv = g_acc[bb][idx++];
                    Jt[k][l] = vv; Jt[l][k] = vv;
                }
            float tr = 0.0f;
#pragma unroll
            for (int k = 0; k < 6; k++) tr += Jt[k][k];
            float lam = tr * 1e-6f;
#pragma unroll
            for (int i = 0; i < 6; i++) {
#pragma unroll
                for (int j = 0; j < 6; j++) M[i][j] = Jt[i][j] + (i == j ? lam : 0.0f);
                M[i][6] = g_acc[bb][21+i];
            }
        }
        for (int k = 0; k < 6; k++) {
            int piv = k; float mx = fabsf(M[k][k]);
            for (int i = k+1; i < 6; i++) {
                float a = fabsf(M[i][k]);
                if (a > mx) { mx = a; piv = i; }
            }
            if (piv != k)
                for (int j = k; j < 7; j++) { float tmp = M[k][j]; M[k][j] = M[piv][j]; M[piv][j] = tmp; }
            float inv = 1.0f / M[k][k];
            for (int i = k+1; i < 6; i++) {
                float f = M[i][k] * inv;
                for (int j = k; j < 7; j++) M[i][j] -= f * M[k][j];
            }
        }
        float xi[6];
        for (int i = 5; i >= 0; i--) {
            float s = M[i][6];
            for (int j = i+1; j < 6; j++) s -= M[i][j] * xi[j];
            xi[i] = s / M[i][i];
        }

        float dR[9];
        rodrigues(-xi[0], -xi[1], -xi[2], dR);
        float dt[3];
        dt[0] = -(dR[0]*xi[3] + dR[1]*xi[4] + dR[2]*xi[5]);
        dt[1] = -(dR[3]*xi[3] + dR[4]*xi[4] + dR[5]*xi[5]);
        dt[2] = -(dR[6]*xi[3] + dR[7]*xi[4] + dR[8]*xi[5]);

        float Rb[9], tb[3];
#pragma unroll
        for (int i = 0; i < 9; i++) Rb[i] = g_R[bb][i];
#pragma unroll
        for (int i = 0; i < 3; i++) tb[i] = g_t[bb][i];

        float nt[3], nR[9];
#pragma unroll
        for (int i = 0; i < 3; i++)
            nt[i] = Rb[i*3+0]*dt[0] + Rb[i*3+1]*dt[1] + Rb[i*3+2]*dt[2] + tb[i];
#pragma unroll
        for (int i = 0; i < 3; i++)
#pragma unroll
            for (int j = 0; j < 3; j++)
                nR[i*3+j] = Rb[i*3+0]*dR[0*3+j] + Rb[i*3+1]*dR[1*3+j] + Rb[i*3+2]*dR[2*3+j];

#pragma unroll
        for (int i = 0; i < 9; i++) g_R[bb][i] = nR[i];
#pragma unroll
        for (int i = 0; i < 3; i++) g_t[bb][i] = nt[i];
#pragma unroll
        for (int k = 0; k < 27; k++) g_acc[bb][k] = 0.0f;

        if (last) {
#pragma unroll
            for (int i = 0; i < 9; i++) out[bb*12 + i] = nR[i];
#pragma unroll
            for (int i = 0; i < 3; i++) out[bb*12 + 9 + i] = nt[i];
        }
    }
}

// ---------------- launch ----------------
extern "C" void kernel_launch(void* const* d_in, const int* in_sizes, int n_in,
                              void* d_out, int out_size) {
    const float* twist0 = (const float*)d_in[0];
    const float* x0     = (const float*)d_in[1];
    const float* x1     = (const float*)d_in[2];
    const float* invD0  = (const float*)d_in[3];
    const float* invD1  = (const float*)d_in[4];
    const float* sigma0 = (const float*)d_in[5];
    const float* sigma1 = (const float*)d_in[6];
    const float* Kmat   = (const float*)d_in[7];
    float* out = (float*)d_out;

    packKernel<<<BB*NN/2/256, 256>>>(twist0, x0, sigma0, x1, sigma1);
    for (int it = 0; it < 3; ++it) {
        dim3 grid(NN/2/256, BB);
        iterKernel<<<grid, 256>>>(invD0, invD1, Kmat, out, it == 2);
    }
}

// round 5
// speedup vs baseline: 1.6856x; 1.6856x over previous
#include <cuda_runtime.h>
#include <cuda_fp16.h>
#include <math.h>

#define BB 8
#define CC 16
#define HH 240
#define WW 320
#define NN (HH*WW)
#define BCN (BB*CC*NN)
#define ITER_BLOCKS (NN/2/256*BB)   // 150*8 = 1200

// ---------------- device-global state (no allocations allowed) ----------------
__device__ float g_R[BB][9];
__device__ float g_t[BB][3];
__device__ float g_acc[BB][27];          // 21 upper-tri JtWJ + 6 Rhs
__device__ unsigned int g_count;         // last-block counter (zero at load; reset after use)
__device__ uint2 g_cen[BCN];             // plane-major per (c,p): {half2(a,g), half2(x0, sigma0^2)}
__device__ __half2 g_gath[BCN];          // plane-major per (c,p): half2(x1, sigma1)

__device__ __forceinline__ unsigned pack_h2(float a, float b) {
    __half2 h = __floats2half2_rn(a, b);
    return *(unsigned*)&h;
}
__device__ __forceinline__ __half2 as_h2(unsigned u) { return *(__half2*)&u; }

__device__ __forceinline__ void rodrigues(float wx, float wy, float wz, float* R) {
    float th = sqrtf(wx*wx + wy*wy + wz*wz) + 1e-12f;
    float inv = 1.0f / th;
    float ax = wx*inv, ay = wy*inv, az = wz*inv;
    float s = sinf(th), c = cosf(th), mc = 1.0f - c;
    R[0] = c + mc*ax*ax;     R[1] = mc*ax*ay - s*az;  R[2] = mc*ax*az + s*ay;
    R[3] = mc*ax*ay + s*az;  R[4] = c + mc*ay*ay;     R[5] = mc*ay*az - s*ax;
    R[6] = mc*ax*az - s*ay;  R[7] = mc*ay*az + s*ax;  R[8] = c + mc*az*az;
}

// ---------------- pack: sobel + fp16 packing (plane-major), init fused ----------------
__global__ __launch_bounds__(256)
void packKernel(const float* __restrict__ twist0, const float* __restrict__ x0,
                const float* __restrict__ sigma0, const float* __restrict__ x1,
                const float* __restrict__ sigma1) {
    if (blockIdx.x == 0 && threadIdx.x < BB) {      // fused init
        int b = threadIdx.x;
        rodrigues(twist0[b*6+0], twist0[b*6+1], twist0[b*6+2], g_R[b]);
        g_t[b][0] = twist0[b*6+3];
        g_t[b][1] = twist0[b*6+4];
        g_t[b][2] = twist0[b*6+5];
#pragma unroll
        for (int k = 0; k < 27; k++) g_acc[b][k] = 0.0f;
    }

    int t = blockIdx.x * 256 + threadIdx.x;     // one thread = 4 horizontal pixels, one channel
    int idx4 = t * 4;
    if (idx4 >= BCN) return;
    int bc = idx4 / NN;
    int p4 = idx4 - bc*NN;
    int v  = p4 / WW;
    int u0 = p4 - v*WW;                          // u0 % 4 == 0, row-contained

    const float* img = x0 + (size_t)bc*NN;
    int vm = max(v-1, 0)*WW, v0 = v*WW, vp = min(v+1, HH-1)*WW;
    int ul = max(u0-1, 0);
    int ur = min(u0+4, WW-1);

    float top[6], mid[6], bot[6];
    {
        float4 c;
        c = *(const float4*)(img + vm + u0);
        top[0]=img[vm+ul]; top[1]=c.x; top[2]=c.y; top[3]=c.z; top[4]=c.w; top[5]=img[vm+ur];
        c = *(const float4*)(img + v0 + u0);
        mid[0]=img[v0+ul]; mid[1]=c.x; mid[2]=c.y; mid[3]=c.z; mid[4]=c.w; mid[5]=img[v0+ur];
        c = *(const float4*)(img + vp + u0);
        bot[0]=img[vp+ul]; bot[1]=c.x; bot[2]=c.y; bot[3]=c.z; bot[4]=c.w; bot[5]=img[vp+ur];
    }

    float4 s0v = *(const float4*)(sigma0 + idx4);
    float s0a[4] = {s0v.x, s0v.y, s0v.z, s0v.w};

    uint2 cen[4];
#pragma unroll
    for (int i = 0; i < 4; i++) {
        float tl = top[i], tc_ = top[i+1], tr = top[i+2];
        float ml = mid[i],                 mr = mid[i+2];
        float bl = bot[i], bc_ = bot[i+1], br = bot[i+2];
        float dx = tr - tl + 2.0f*(mr - ml) + (br - bl);
        float dy = bl - tl + 2.0f*(bc_ - tc_) + (br - tr);
        float rinv = rsqrtf(dx*dx + dy*dy + 1e-8f);
        cen[i].x = pack_h2(dx*rinv, dy*rinv);
        cen[i].y = pack_h2(mid[i+1], s0a[i]*s0a[i]);
    }
    *(uint4*)&g_cen[idx4]   = make_uint4(cen[0].x, cen[0].y, cen[1].x, cen[1].y);
    *(uint4*)&g_cen[idx4+2] = make_uint4(cen[2].x, cen[2].y, cen[3].x, cen[3].y);

    float4 xv = *(const float4*)(x1 + idx4);
    float4 sv = *(const float4*)(sigma1 + idx4);
    *(uint4*)&g_gath[idx4] = make_uint4(pack_h2(xv.x, sv.x), pack_h2(xv.y, sv.y),
                                        pack_h2(xv.z, sv.z), pack_h2(xv.w, sv.w));
}

// ---------------- fused per-iteration accumulation + last-block solve ----------------
__global__ __launch_bounds__(256)
void iterKernel(const float* __restrict__ invD0, const float* __restrict__ invD1,
                const float* __restrict__ Kmat, float* __restrict__ out, int last)
{
    const int b  = blockIdx.y;
    const int p2 = (blockIdx.x * 256 + threadIdx.x) * 2;

    float acc[27];
#pragma unroll
    for (int k = 0; k < 27; k++) acc[k] = 0.0f;

    {
        const float fx = Kmat[b*4+0], fy = Kmat[b*4+1];
        const float cx = Kmat[b*4+2], cy = Kmat[b*4+3];
        const float ifx = 1.0f/fx, ify = 1.0f/fy;
        const float* Rb = g_R[b];
        const float* tb = g_t[b];

        int vpix = p2 / WW;
        int u0   = p2 - vpix*WW;
        float y  = ((float)vpix - cy) * ify;
        float2 d2 = *(const float2*)(invD0 + (size_t)b*NN + p2);
        float dd[2] = {d2.x, d2.y};

        float xs_[2], valid[2];
        __half2 w00h[2], w01h[2], w10h[2], w11h[2];
        int o00[2], o01[2], o10[2], o11[2];
        const float* D1 = invD1 + (size_t)b*NN;

#pragma unroll
        for (int i = 0; i < 2; i++) {
            float x = ((float)(u0 + i) - cx) * ifx;
            xs_[i] = x;
            float d = dd[i];
            float X = Rb[0]*x + Rb[1]*y + Rb[2] + tb[0]*d;
            float Y = Rb[3]*x + Rb[4]*y + Rb[5] + tb[1]*d;
            float S = Rb[6]*x + Rb[7]*y + Rb[8] + tb[2]*d;
            float invS = __fdividef(1.0f, S);
            float u = X * invS * fx + cx;
            float v = Y * invS * fy + cy;
            float invz = d * invS;

            float uc = fminf(fmaxf(u, 0.0f), (float)(WW-1));
            float vc = fminf(fmaxf(v, 0.0f), (float)(HH-1));
            float x0f = floorf(uc), y0f = floorf(vc);
            float wx = uc - x0f, wy = vc - y0f;
            int xi0 = (int)x0f, yi0 = (int)y0f;
            int xi1 = min(xi0 + 1, WW-1), yi1 = min(yi0 + 1, HH-1);
            float w00 = (1.0f-wx)*(1.0f-wy), w01 = wx*(1.0f-wy);
            float w10 = (1.0f-wx)*wy,        w11 = wx*wy;
            o00[i] = yi0*WW + xi0; o01[i] = yi0*WW + xi1;
            o10[i] = yi1*WW + xi0; o11[i] = yi1*WW + xi1;
            w00h[i] = __float2half2_rn(w00); w01h[i] = __float2half2_rn(w01);
            w10h[i] = __float2half2_rn(w10); w11h[i] = __float2half2_rn(w11);

            float dz = D1[o00[i]]*w00 + D1[o01[i]]*w01 + D1[o10[i]]*w10 + D1[o11[i]]*w11;
            bool inlier = invz > dz - 0.1f;
            bool inview = (u > 0.0f) && (u < (float)WW) && (v > 0.0f) && (v < (float)HH);
            valid[i] = (inlier && inview) ? 1.0f : 0.0f;
        }

        float Saa[2] = {0,0}, Sab[2] = {0,0}, Sbb[2] = {0,0};
        float Sar[2] = {0,0}, Sbr[2] = {0,0};
        const size_t cbase = (size_t)b*CC*NN + p2;
#pragma unroll 4
        for (int c = 0; c < CC; c++) {
            size_t base = cbase + (size_t)c*NN;
            uint4 cv = __ldg((const uint4*)&g_cen[base]);
            const __half2* G = g_gath + (base - p2);   // (b,c) plane base
            unsigned int agu[2] = {cv.x, cv.z};
            unsigned int xsu[2] = {cv.y, cv.w};
#pragma unroll
            for (int i = 0; i < 2; i++) {
                __half2 h00 = __ldg(G + o00[i]);
                __half2 h01 = __ldg(G + o01[i]);
                __half2 h10 = __ldg(G + o10[i]);
                __half2 h11 = __ldg(G + o11[i]);
                __half2 fs = __hmul2(h00, w00h[i]);
                fs = __hfma2(h01, w01h[i], fs);
                fs = __hfma2(h10, w10h[i], fs);
                fs = __hfma2(h11, w11h[i], fs);
                float2 frsr = __half22float2(fs);
                float2 ag   = __half22float2(as_h2(agu[i]));
                float2 xss  = __half22float2(as_h2(xsu[i]));
                float s2  = frsr.y*frsr.y + xss.y;
                float wgt = __fdividef(1.0f, s2);
                float res = frsr.x - xss.x;
                float aw = ag.x*wgt, gw = ag.y*wgt;
                Saa[i] += aw*ag.x;
                Sab[i] += aw*ag.y;
                Sbb[i] += gw*ag.y;
                Sar[i] += aw*res;
                Sbr[i] += gw*res;
            }
        }

        // expand each pixel's S into 27 accumulators
#pragma unroll
        for (int i = 0; i < 2; i++) {
            float vmask = valid[i];
            float saa = Saa[i]*vmask, sab = Sab[i]*vmask, sbb = Sbb[i]*vmask;
            float sar = Sar[i]*vmask, sbr = Sbr[i]*vmask;
            float x = xs_[i], d = dd[i];
            float xy = x*y;
            float Jx[6], Jy[6];
            Jx[0] = -xy*fx;          Jx[1] = (1.0f + x*x)*fx; Jx[2] = -y*fx;
            Jx[3] = d*fx;            Jx[4] = 0.0f;            Jx[5] = -d*x*fx;
            Jy[0] = -(1.0f+y*y)*fy;  Jy[1] = xy*fy;           Jy[2] = x*fy;
            Jy[3] = 0.0f;            Jy[4] = d*fy;            Jy[5] = -d*y*fy;
            int idx = 0;
#pragma unroll
            for (int k = 0; k < 6; k++) {
#pragma unroll
                for (int l = k; l < 6; l++) {
                    acc[idx++] += saa*Jx[k]*Jx[l] + sab*(Jx[k]*Jy[l] + Jy[k]*Jx[l]) + sbb*Jy[k]*Jy[l];
                }
            }
#pragma unroll
            for (int k = 0; k < 6; k++) acc[21+k] += sar*Jx[k] + sbr*Jy[k];
        }
    }

    // ---- block reduction of 27 values, then per-block atomicAdd ----
#pragma unroll
    for (int k = 0; k < 27; k++) {
#pragma unroll
        for (int off = 16; off > 0; off >>= 1)
            acc[k] += __shfl_down_sync(0xFFFFFFFFu, acc[k], off);
    }
    __shared__ float sm[27][8];
    int lane = threadIdx.x & 31;
    int warp = threadIdx.x >> 5;
    if (lane == 0) {
#pragma unroll
        for (int k = 0; k < 27; k++) sm[k][warp] = acc[k];
    }
    __syncthreads();
    if (threadIdx.x < 27) {
        float s = 0.0f;
#pragma unroll
        for (int w = 0; w < 8; w++) s += sm[threadIdx.x][w];
        atomicAdd(&g_acc[blockIdx.y][threadIdx.x], s);
        __threadfence();
    }
    __syncthreads();

    // ---- last-block-does-solve (threadFenceReduction pattern) ----
    __shared__ bool sLast;
    if (threadIdx.x == 0) {
        unsigned int done = atomicAdd(&g_count, 1u);
        sLast = (done == ITER_BLOCKS - 1);
    }
    __syncthreads();
    if (!sLast) return;
    if (threadIdx.x == 0) g_count = 0;
    __threadfence();

    if (threadIdx.x < BB) {
        int bb = threadIdx.x;
        float M[6][7];
        {
            float Jt[6][6];
            int idx = 0;
#pragma unroll
            for (int k = 0; k < 6; k++)
#pragma unroll
                for (int l = k; l < 6; l++) {
                    float vv = g_acc[bb][idx++];
                    Jt[k][l] = vv; Jt[l][k] = vv;
                }
            float tr = 0.0f;
#pragma unroll
            for (int k = 0; k < 6; k++) tr += Jt[k][k];
            float lam = tr * 1e-6f;
#pragma unroll
            for (int i = 0; i < 6; i++) {
#pragma unroll
                for (int j = 0; j < 6; j++) M[i][j] = Jt[i][j] + (i == j ? lam : 0.0f);
                M[i][6] = g_acc[bb][21+i];
            }
        }
        for (int k = 0; k < 6; k++) {
            int piv = k; float mx = fabsf(M[k][k]);
            for (int i = k+1; i < 6; i++) {
                float a = fabsf(M[i][k]);
                if (a > mx) { mx = a; piv = i; }
            }
            if (piv != k)
                for (int j = k; j < 7; j++) { float tmp = M[k][j]; M[k][j] = M[piv][j]; M[piv][j] = tmp; }
            float inv = 1.0f / M[k][k];
            for (int i = k+1; i < 6; i++) {
                float f = M[i][k] * inv;
                for (int j = k; j < 7; j++) M[i][j] -= f * M[k][j];
            }
        }
        float xi[6];
        for (int i = 5; i >= 0; i--) {
            float s = M[i][6];
            for (int j = i+1; j < 6; j++) s -= M[i][j] * xi[j];
            xi[i] = s / M[i][i];
        }

        float dR[9];
        rodrigues(-xi[0], -xi[1], -xi[2], dR);
        float dt[3];
        dt[0] = -(dR[0]*xi[3] + dR[1]*xi[4] + dR[2]*xi[5]);
        dt[1] = -(dR[3]*xi[3] + dR[4]*xi[4] + dR[5]*xi[5]);
        dt[2] = -(dR[6]*xi[3] + dR[7]*xi[4] + dR[8]*xi[5]);

        float Rb[9], tb[3];
#pragma unroll
        for (int i = 0; i < 9; i++) Rb[i] = g_R[bb][i];
#pragma unroll
        for (int i = 0; i < 3; i++) tb[i] = g_t[bb][i];

        float nt[3], nR[9];
#pragma unroll
        for (int i = 0; i < 3; i++)
            nt[i] = Rb[i*3+0]*dt[0] + Rb[i*3+1]*dt[1] + Rb[i*3+2]*dt[2] + tb[i];
#pragma unroll
        for (int i = 0; i < 3; i++)
#pragma unroll
            for (int j = 0; j < 3; j++)
                nR[i*3+j] = Rb[i*3+0]*dR[0*3+j] + Rb[i*3+1]*dR[1*3+j] + Rb[i*3+2]*dR[2*3+j];

#pragma unroll
        for (int i = 0; i < 9; i++) g_R[bb][i] = nR[i];
#pragma unroll
        for (int i = 0; i < 3; i++) g_t[bb][i] = nt[i];
#pragma unroll
        for (int k = 0; k < 27; k++) g_acc[bb][k] = 0.0f;

        if (last) {
#pragma unroll
            for (int i = 0; i < 9; i++) out[bb*12 + i] = nR[i];
#pragma unroll
            for (int i = 0; i < 3; i++) out[bb*12 + 9 + i] = nt[i];
        }
    }
}

// ---------------- launch ----------------
extern "C" void kernel_launch(void* const* d_in, const int* in_sizes, int n_in,
                              void* d_out, int out_size) {
    const float* twist0 = (const float*)d_in[0];
    const float* x0     = (const float*)d_in[1];
    const float* x1     = (const float*)d_in[2];
    const float* invD0  = (const float*)d_in[3];
    const float* invD1  = (const float*)d_in[4];
    const float* sigma0 = (const float*)d_in[5];
    const float* sigma1 = (const float*)d_in[6];
    const float* Kmat   = (const float*)d_in[7];
    float* out = (float*)d_out;

    packKernel<<<BCN/4/256, 256>>>(twist0, x0, sigma0, x1, sigma1);
    for (int it = 0; it < 3; ++it) {
        dim3 grid(NN/2/256, BB);
        iterKernel<<<grid, 256>>>(invD0, invD1, Kmat, out, it == 2);
    }
}